// round 5
// baseline (speedup 1.0000x reference)
#include <cuda_runtime.h>
#include <cstdint>

// MergedEmbeddingBag: T=26 tables, R=100000 rows, D=128, B=4096, L=20.
// W: [T, R, D] fp32.  indices: [T, B, L] int32.  out: [T, B, D] fp32.
// Odd tables -> MEAN (/L), even -> SUM.
//
// One warp per bag; lane owns one float4 -> each row gather is one fully
// coalesced 512B warp transaction (4x128B lines). This round: FULL 20-deep
// front-batched gather (launch_bounds(256,2) => ~128-reg budget) to test
// whether the 83% DRAM plateau is latency exposure or the HBM ceiling.

constexpr int T = 26;
constexpr int R = 100000;
constexpr int D = 128;
constexpr int B = 4096;
constexpr int L = 20;
constexpr int BAGS = T * B;           // 106496 bags
constexpr int D4 = D / 4;             // 32 float4 per row -> 1 per lane

__global__ __launch_bounds__(256, 2)
void merged_embedding_bag_kernel(const float4* __restrict__ W4,
                                 const int* __restrict__ indices,
                                 float4* __restrict__ out4)
{
    const int gwarp = (blockIdx.x * blockDim.x + threadIdx.x) >> 5;
    const int lane  = threadIdx.x & 31;
    if (gwarp >= BAGS) return;

    const int t = gwarp / B;                 // table id
    const int* __restrict__ ip = indices + (size_t)gwarp * L;

    const float4* __restrict__ wt = W4 + (size_t)t * (size_t)R * D4;

    // Load all 20 indices (warp-broadcast txns; 16B-aligned so ptxas can
    // vectorize to LDG.128 x5).
    int ridx[L];
#pragma unroll
    for (int l = 0; l < L; l++) {
        int v = ip[l];
        v = v < 0 ? 0 : (v >= R ? R - 1 : v);   // defensive, free vs DRAM lat
        ridx[l] = v;
    }

    // Full front batch: issue all 20 LDG.128 before any consumption.
    float4 v[L];
#pragma unroll
    for (int l = 0; l < L; l++)
        v[l] = __ldg(&wt[(size_t)ridx[l] * D4 + lane]);

    float ax = 0.f, ay = 0.f, az = 0.f, aw = 0.f;
#pragma unroll
    for (int l = 0; l < L; l++) {
        ax += v[l].x; ay += v[l].y; az += v[l].z; aw += v[l].w;
    }

    const float s = (t & 1) ? (1.0f / (float)L) : 1.0f;
    float4 o;
    o.x = ax * s; o.y = ay * s; o.z = az * s; o.w = aw * s;

    // Streaming store: evict-first, keep L2 for the table working set.
    __stcs(&out4[(size_t)gwarp * D4 + lane], o);
}

extern "C" void kernel_launch(void* const* d_in, const int* in_sizes, int n_in,
                              void* d_out, int out_size)
{
    const float4* W4 = (const float4*)d_in[0];
    const int* indices = (const int*)d_in[1];
    float4* out4 = (float4*)d_out;

    const int threads = 256;                      // 8 warps / block
    const int warps_per_block = threads / 32;
    const int blocks = (BAGS + warps_per_block - 1) / warps_per_block;  // 13312

    merged_embedding_bag_kernel<<<blocks, threads>>>(W4, indices, out4);
}

// round 6
// speedup vs baseline: 1.0513x; 1.0513x over previous
#include <cuda_runtime.h>
#include <cstdint>

// MergedEmbeddingBag: T=26 tables, R=100000 rows, D=128, B=4096, L=20.
// W: [T, R, D] fp32.  indices: [T, B, L] int32.  out: [T, B, D] fp32.
// Odd tables -> MEAN (/L), even -> SUM.
//
// One warp per bag; lane owns one float4 -> each row gather is one fully
// coalesced 512B warp transaction. Two front-batched groups of 10 LDG.128
// (the measured-best MLP shape), 32-bit offset addressing from the per-table
// base (table = 51MB < 4GB) to cut 64-bit IMAD chains and register pressure,
// occupancy pinned at 5 blocks/SM (the flat-top of the measured occ curve).

constexpr int T = 26;
constexpr int R = 100000;
constexpr int D = 128;
constexpr int B = 4096;
constexpr int L = 20;
constexpr int BAGS = T * B;           // 106496 bags
constexpr int D4 = D / 4;             // 32 float4 per row -> 1 per lane
constexpr int HALF = L / 2;           // 10

__global__ __launch_bounds__(256, 5)
void merged_embedding_bag_kernel(const float4* __restrict__ W4,
                                 const int* __restrict__ indices,
                                 float4* __restrict__ out4)
{
    const int gwarp = (blockIdx.x * blockDim.x + threadIdx.x) >> 5;
    const int lane  = threadIdx.x & 31;
    if (gwarp >= BAGS) return;

    const int t = gwarp / B;                 // table id
    const int* __restrict__ ip = indices + (size_t)gwarp * L;

    // Per-table base; all row offsets from here fit in 32 bits (51 MB table).
    const float4* __restrict__ wt = W4 + (size_t)t * (size_t)R * D4;

    // 20 indices up front (warp-broadcast; vectorizes to LDG.128 x5).
    // Convert immediately to 32-bit float4 offsets (row*32 + lane <= 3.2M).
    unsigned off[L];
#pragma unroll
    for (int l = 0; l < L; l++) {
        int v = ip[l];
        v = v < 0 ? 0 : (v >= R ? R - 1 : v);   // defensive, free vs DRAM lat
        off[l] = (unsigned)v * (unsigned)D4 + (unsigned)lane;
    }

    float ax = 0.f, ay = 0.f, az = 0.f, aw = 0.f;

    // ---- batch 1: 10 loads in flight, then accumulate ----
    {
        float4 v[HALF];
#pragma unroll
        for (int l = 0; l < HALF; l++)
            v[l] = __ldg(wt + off[l]);
#pragma unroll
        for (int l = 0; l < HALF; l++) {
            ax += v[l].x; ay += v[l].y; az += v[l].z; aw += v[l].w;
        }
    }
    // ---- batch 2 ----
    {
        float4 v[HALF];
#pragma unroll
        for (int l = 0; l < HALF; l++)
            v[l] = __ldg(wt + off[HALF + l]);
#pragma unroll
        for (int l = 0; l < HALF; l++) {
            ax += v[l].x; ay += v[l].y; az += v[l].z; aw += v[l].w;
        }
    }

    const float s = (t & 1) ? (1.0f / (float)L) : 1.0f;
    float4 o;
    o.x = ax * s; o.y = ay * s; o.z = az * s; o.w = aw * s;

    // Streaming store: evict-first, keep L2 for the table working set.
    __stcs(&out4[(size_t)gwarp * D4 + lane], o);
}

extern "C" void kernel_launch(void* const* d_in, const int* in_sizes, int n_in,
                              void* d_out, int out_size)
{
    const float4* W4 = (const float4*)d_in[0];
    const int* indices = (const int*)d_in[1];
    float4* out4 = (float4*)d_out;

    const int threads = 256;                      // 8 warps / block
    const int warps_per_block = threads / 32;
    const int blocks = (BAGS + warps_per_block - 1) / warps_per_block;  // 13312

    merged_embedding_bag_kernel<<<blocks, threads>>>(W4, indices, out4);
}

// round 7
// speedup vs baseline: 1.0638x; 1.0119x over previous
#include <cuda_runtime.h>
#include <cstdint>

// MergedEmbeddingBag: T=26 tables, R=100000 rows, D=128, B=4096, L=20.
// W: [T, R, D] fp32.  indices: [T, B, L] int32.  out: [T, B, D] fp32.
// Odd tables -> MEAN (/L), even -> SUM.
//
// One warp per bag; lane owns one float4 -> each row gather is one fully
// coalesced 512B warp transaction. Two front-batched groups of 10 loads
// (measured-best MLP shape). Row gathers use __ldcg: L1 can never hit
// (random over 51MB, L1 flushed per launch) so skip L1 allocation entirely,
// cutting L1tex wavefront-queue pressure (cross-CTA spread mechanism).
// Output via __stcs (evict-first) to keep L2 for the table working set.

constexpr int T = 26;
constexpr int R = 100000;
constexpr int D = 128;
constexpr int B = 4096;
constexpr int L = 20;
constexpr int BAGS = T * B;           // 106496 bags
constexpr int D4 = D / 4;             // 32 float4 per row -> 1 per lane
constexpr int HALF = L / 2;           // 10

__global__ __launch_bounds__(256, 5)
void merged_embedding_bag_kernel(const float4* __restrict__ W4,
                                 const int* __restrict__ indices,
                                 float4* __restrict__ out4)
{
    const int gwarp = (blockIdx.x * blockDim.x + threadIdx.x) >> 5;
    const int lane  = threadIdx.x & 31;
    if (gwarp >= BAGS) return;

    const int t = gwarp / B;                 // table id
    const int* __restrict__ ip = indices + (size_t)gwarp * L;

    // Per-table base; all row offsets from here fit in 32 bits (51 MB table).
    const float4* __restrict__ wt = W4 + (size_t)t * (size_t)R * D4;

    // 20 indices up front (warp-broadcast; vectorizes to LDG.128 x5),
    // converted to 32-bit float4 offsets (row*32 + lane <= 3.2M).
    unsigned off[L];
#pragma unroll
    for (int l = 0; l < L; l++) {
        int v = ip[l];
        v = v < 0 ? 0 : (v >= R ? R - 1 : v);   // defensive, free vs DRAM lat
        off[l] = (unsigned)v * (unsigned)D4 + (unsigned)lane;
    }

    float ax = 0.f, ay = 0.f, az = 0.f, aw = 0.f;

    // ---- batch 1: 10 loads in flight, then accumulate ----
    {
        float4 v[HALF];
#pragma unroll
        for (int l = 0; l < HALF; l++)
            v[l] = __ldcg(wt + off[l]);          // L2-only: no L1 allocation
#pragma unroll
        for (int l = 0; l < HALF; l++) {
            ax += v[l].x; ay += v[l].y; az += v[l].z; aw += v[l].w;
        }
    }
    // ---- batch 2 ----
    {
        float4 v[HALF];
#pragma unroll
        for (int l = 0; l < HALF; l++)
            v[l] = __ldcg(wt + off[HALF + l]);
#pragma unroll
        for (int l = 0; l < HALF; l++) {
            ax += v[l].x; ay += v[l].y; az += v[l].z; aw += v[l].w;
        }
    }

    const float s = (t & 1) ? (1.0f / (float)L) : 1.0f;
    float4 o;
    o.x = ax * s; o.y = ay * s; o.z = az * s; o.w = aw * s;

    // Streaming store: evict-first, keep L2 for the table working set.
    __stcs(&out4[(size_t)gwarp * D4 + lane], o);
}

extern "C" void kernel_launch(void* const* d_in, const int* in_sizes, int n_in,
                              void* d_out, int out_size)
{
    const float4* W4 = (const float4*)d_in[0];
    const int* indices = (const int*)d_in[1];
    float4* out4 = (float4*)d_out;

    const int threads = 256;                      // 8 warps / block
    const int warps_per_block = threads / 32;
    const int blocks = (BAGS + warps_per_block - 1) / warps_per_block;  // 13312

    merged_embedding_bag_kernel<<<blocks, threads>>>(W4, indices, out4);
}